// round 16
// baseline (speedup 1.0000x reference)
#include <cuda_runtime.h>
#include <cuda_bf16.h>
#include <cstdint>
#include <math.h>

// Problem dims
#define T_STEPS 256
#define OBS     512
#define ACT     32
#define HID     1024
#define MSG     128
#define PE      128
#define GATES   512          // 4*PE
#define IN_DIM  33           // 1 + ACT
#define INV_SC  0.08838834764831843f   // 1/sqrt(128)

typedef unsigned long long u64t;
typedef unsigned int       u32t;

// ---------------- device scratch (static, no allocation) ----------------
__device__ __align__(16) float  g_XN [T_STEPS * OBS];      // normalized obs [t][j]
__device__ __align__(16) float  g_SH [T_STEPS * GATES];    // per-step gate constant [t][r]
__device__ __align__(16) float  g_W0 [GATES];              // W_ih[:,0]
__device__ __align__(16) float  g_q  [HID * MSG];          // q = pos @ Wq^T + bq, [i][m]
__device__ __align__(16) float  g_QWT[PE * HID];           // inv * (q @ Wk), [p][i]
__device__ __align__(16) float  g_qbs[HID];                // inv * (q . bk)
// W_hh bf16 hi/lo in mma a-fragment layout: [tile(mt*8+kt)][lane][q] packed bf16x2
__device__ __align__(16) u32t g_WAh[256 * 128];
__device__ __align__(16) u32t g_WAl[256 * 128];
// bf16 split operands for the tensor-core attention GEMM
__device__ __align__(256) __nv_bfloat16 g_QAh[HID * PE];   // A hi: [i][p]
__device__ __align__(256) __nv_bfloat16 g_QAl[HID * PE];   // A lo: [i][p]
__device__ __align__(256) __nv_bfloat16 g_HBh[(size_t)T_STEPS * OBS * PE]; // B hi: [t][j][p]
__device__ __align__(256) __nv_bfloat16 g_HBl[(size_t)T_STEPS * OBS * PE]; // B lo: [t][j][p]

// ---------------- cp.async ----------------
__device__ __forceinline__ void cp16(u32t dst, const void* src) {
    asm volatile("cp.async.cg.shared.global [%0], [%1], 16;" :: "r"(dst), "l"(src));
}
__device__ __forceinline__ void cp_commit() {
    asm volatile("cp.async.commit_group;");
}
__device__ __forceinline__ void cp_wait0() {
    asm volatile("cp.async.wait_group 0;" ::: "memory");
}

// ---------------- ldmatrix / mma.sync (sm_80 baseline, ptxas-safe) ----------------
#define LDSM4(r, addr) \
    asm volatile("ldmatrix.sync.aligned.m8n8.x4.shared.b16 {%0,%1,%2,%3}, [%4];" \
        : "=r"((r)[0]), "=r"((r)[1]), "=r"((r)[2]), "=r"((r)[3]) : "r"(addr))

__device__ __forceinline__ void mma_bf16(float* d, const u32t* a, u32t b0, u32t b1) {
    asm volatile(
        "mma.sync.aligned.m16n8k16.row.col.f32.bf16.bf16.f32 "
        "{%0,%1,%2,%3}, {%4,%5,%6,%7}, {%8,%9}, {%0,%1,%2,%3};"
        : "+f"(d[0]), "+f"(d[1]), "+f"(d[2]), "+f"(d[3])
        : "r"(a[0]), "r"(a[1]), "r"(a[2]), "r"(a[3]), "r"(b0), "r"(b1));
}

// ---------------- fast-but-accurate activations ----------------
__device__ __forceinline__ float sig_f(float x) {
    return __fdividef(1.f, 1.f + __expf(-x));
}
__device__ __forceinline__ float tanh_f(float x) {
    float ax = fabsf(x);
    float e  = __expf(-2.f * ax);
    float r  = __fdividef(1.f - e, 1.f + e);
    return copysignf(r, x);
}

// ======================================================================
// K0: normalized obs + per-step gate constants (+W0 once). grid(T_STEPS), block(512)
// ======================================================================
__global__ void k_pre1(const float* __restrict__ obs,
                       const float* __restrict__ act,
                       const float* __restrict__ shift,
                       const float* __restrict__ scale,
                       const float* __restrict__ W_ih,
                       const float* __restrict__ b_ih,
                       const float* __restrict__ b_hh) {
    __shared__ float actS[ACT];
    int t = blockIdx.x;
    int r = threadIdx.x;
    if (r < ACT) actS[r] = act[t * ACT + r];
    __syncthreads();

    g_XN[t * OBS + r] = (obs[t * OBS + r] - shift[r]) / (scale[r] + 1e-8f);
    if (t == 0) g_W0[r] = W_ih[r * IN_DIM];

    float sh = b_ih[r] + b_hh[r];
    const float* wrow = W_ih + r * IN_DIM + 1;
#pragma unroll 8
    for (int a = 0; a < ACT; a++) sh = fmaf(wrow[a], actS[a], sh);
    g_SH[t * GATES + r] = sh;
}

// ======================================================================
// K0b: W_hh -> bf16 hi/lo a-fragment layout. grid(256 tiles), block(128)
// tile = mt*8+kt ; thread = lane*4+q ; q -> (dr,dc) = ((q&1)*8, (q>>1)*8)
// a-frag element (r,c): r = mt*16 + lane/4 + dr ; c = kt*16 + (lane%4)*2 + dc
// ======================================================================
__global__ void k_prew(const float* __restrict__ W_hh) {
    int tile = blockIdx.x;
    int l = threadIdx.x >> 2;
    int q = threadIdx.x & 3;
    int mt = tile >> 3, kt = tile & 7;
    int r = mt * 16 + (l >> 2) + (q & 1) * 8;
    int c = kt * 16 + (l & 3) * 2 + (q >> 1) * 8;
    float v0 = W_hh[r * PE + c], v1 = W_hh[r * PE + c + 1];
    __nv_bfloat16 h0 = __float2bfloat16(v0), h1 = __float2bfloat16(v1);
    float r0 = v0 - __bfloat162float(h0), r1 = v1 - __bfloat162float(h1);
    __nv_bfloat16 e0 = __float2bfloat16(r0), e1 = __float2bfloat16(r1);
    u32t hi = (u32t)__bfloat16_as_ushort(h0) | ((u32t)__bfloat16_as_ushort(h1) << 16);
    u32t lo = (u32t)__bfloat16_as_ushort(e0) | ((u32t)__bfloat16_as_ushort(e1) << 16);
    g_WAh[tile * 128 + l * 4 + q] = hi;
    g_WAl[tile * 128 + l * 4 + q] = lo;
}

// ======================================================================
// K1: q = pos @ Wq^T + bq. grid(128) i-tiles of 8, block(256)
// ======================================================================
__global__ void __launch_bounds__(256) k_q(const float* __restrict__ pos,
                                           const float* __restrict__ Wq,
                                           const float* __restrict__ bq) {
    extern __shared__ float sm[];
    float* posS = sm;            // [8][128]
    float* WqT  = sm + 8 * PE;   // [e][m]
    int i0 = blockIdx.x * 8;
    int tid = threadIdx.x;

    for (int idx = tid; idx < 8 * PE; idx += 256) posS[idx] = pos[i0 * PE + idx];
    for (int idx = tid; idx < MSG * PE; idx += 256) {
        int mm = idx >> 7, e = idx & 127;
        WqT[e * MSG + mm] = Wq[idx];
    }
    __syncthreads();

    int m  = tid & 127;
    int ih = tid >> 7;
    float bqm = bq[m];
#pragma unroll
    for (int s = 0; s < 4; s++) {
        int isub = ih * 4 + s;
        float acc = bqm;
#pragma unroll 8
        for (int e = 0; e < PE; e++)
            acc = fmaf(posS[isub * PE + e], WqT[e * MSG + m], acc);
        g_q[(i0 + isub) * MSG + m] = acc;
    }
}

// ======================================================================
// K2: QWT[p][i] = inv*(q@Wk)[i][p]; qbs[i] = inv*q[i].bk
// ======================================================================
__global__ void __launch_bounds__(256) k_qw(const float* __restrict__ Wk,
                                            const float* __restrict__ bk) {
    extern __shared__ float sm[];
    float* qS  = sm;             // [8][128]
    float* WkS = sm + 8 * MSG;   // [m][p]
    int i0 = blockIdx.x * 8;
    int tid = threadIdx.x;

    for (int idx = tid; idx < 8 * MSG; idx += 256) qS[idx] = g_q[i0 * MSG + idx];
    for (int idx = tid; idx < MSG * PE; idx += 256) WkS[idx] = Wk[idx];
    __syncthreads();

    int p  = tid & 127;
    int ih = tid >> 7;
#pragma unroll
    for (int s = 0; s < 4; s++) {
        int isub = ih * 4 + s;
        float acc = 0.f;
#pragma unroll 8
        for (int m = 0; m < MSG; m++)
            acc = fmaf(qS[isub * MSG + m], WkS[m * PE + p], acc);
        g_QWT[p * HID + i0 + isub] = acc * INV_SC;
    }
    if (tid < 8) {
        float acc = 0.f;
#pragma unroll 8
        for (int m = 0; m < MSG; m++) acc = fmaf(qS[tid * MSG + m], bk[m], acc);
        g_qbs[i0 + tid] = acc * INV_SC;
    }
}

// ======================================================================
// K2b: split QWT into bf16 hi/lo, layout [i][p]. grid(128), block(256)
// ======================================================================
__global__ void k_split() {
#pragma unroll
    for (int k = 0; k < 4; k++) {
        int idx = blockIdx.x * 1024 + k * 256 + threadIdx.x;   // 0..131071
        int i = idx >> 7, p = idx & 127;
        float v = g_QWT[p * HID + i];
        __nv_bfloat16 bh = __float2bfloat16(v);
        float rem = v - __bfloat162float(bh);
        g_QAh[idx] = bh;
        g_QAl[idx] = __float2bfloat16(rem);
    }
}

// ======================================================================
// K3: tensor-core LSTM v2. 128 CTAs x 4 chains, 256 threads (8 warps).
// Tile remap: warp w owns tile (g*8 + w) for each gate g -> rows 16w..16w+15
// of ALL FOUR gates -> activation entirely in-register (no gate dump).
// h smem double-buffered -> ONE __syncthreads per step.
// Accumulators split d1 (Wh@hh) / d2 (Wh@hl + Wl@hh) -> shorter HMMA chains.
// Wl fragments for g=0 held in registers; g=1..3 from smem.
// smem: [0,131072) Wl frag table ;
//       h buffers: hh0 @131072, hl0 @133248, hh1 @135424, hl1 @137600
//       each 8 rows x 272B = 2176 B -> total 139776
// ======================================================================
#define LS_WL   0
#define LS_HH0  131072
#define LS_HL0  133248
#define LS_HH1  135424
#define LS_HL1  137600
#define LS_TOT  139776
#define HSTR    272          // bytes per n-row of h buffers (128 bf16 + 8 pad)

__global__ void __launch_bounds__(256, 1) k_lstm_tc() {
    extern __shared__ char smc[];
    uint4* wlS = reinterpret_cast<uint4*>(smc + LS_WL);

    int tid = threadIdx.x, w = tid >> 5, l = tid & 31;
    int j0 = blockIdx.x * 4;

    // stage Wl frag table (128KB) + zero both h double-buffers (8704 B)
    const uint4* gWl4 = reinterpret_cast<const uint4*>(g_WAl);
    for (int i = tid; i < 8192; i += 256) wlS[i] = gWl4[i];
    for (int i = tid; i < 2176; i += 256)
        reinterpret_cast<u32t*>(smc + LS_HH0)[i] = 0u;

    // Wh a-frags -> registers: wh[g][kt] = tile (g*8 + w)
    uint4 wh[4][8];
    {
        const uint4* gWh4 = reinterpret_cast<const uint4*>(g_WAh);
#pragma unroll
        for (int g = 0; g < 4; g++)
#pragma unroll
            for (int kt = 0; kt < 8; kt++)
                wh[g][kt] = gWh4[(((g * 8 + w) * 8) + kt) * 32 + l];
    }
    // Wl a-frags for g=0 in registers
    uint4 wlr[8];
#pragma unroll
    for (int kt = 0; kt < 8; kt++)
        wlr[kt] = gWl4[((w * 8) + kt) * 32 + l];

    // per-lane activation identity: rows r0, r0+8 ; chains c0, c0+1
    int r0 = 16 * w + (l >> 2);
    int c0 = (l & 3) * 2;
    bool active = (l & 3) < 2;

    float w0g[4][2];
#pragma unroll
    for (int g = 0; g < 4; g++) {
        w0g[g][0] = g_W0[g * 128 + r0];
        w0g[g][1] = g_W0[g * 128 + r0 + 8];
    }
    float cst[4] = {0.f, 0.f, 0.f, 0.f};   // c-state per q=(rh*2+cc)

    __syncthreads();

    for (int t = 0; t < T_STEPS; t++) {
        // step constants (issued early; consumed after the mma loop)
        float shv[4][2];
#pragma unroll
        for (int g = 0; g < 4; g++) {
            shv[g][0] = g_SH[t * GATES + g * 128 + r0];
            shv[g][1] = g_SH[t * GATES + g * 128 + r0 + 8];
        }
        float2 xnv = *reinterpret_cast<const float2*>(g_XN + t * OBS + j0 + c0);

        // b-frag bases for this step's read buffer
        const char* rb = smc + ((t & 1) ? LS_HH1 : LS_HH0);
        const char* bh_base = rb + (l >> 2) * HSTR + (l & 3) * 4;
        const char* bl_base = bh_base + (LS_HL0 - LS_HH0);

        float d1[4][4], d2[4][4];
#pragma unroll
        for (int g = 0; g < 4; g++)
#pragma unroll
            for (int q = 0; q < 4; q++) { d1[g][q] = 0.f; d2[g][q] = 0.f; }

#pragma unroll
        for (int kt = 0; kt < 8; kt++) {
            u32t bh0 = *reinterpret_cast<const u32t*>(bh_base + kt * 32);
            u32t bh1 = *reinterpret_cast<const u32t*>(bh_base + kt * 32 + 16);
            u32t bl0 = *reinterpret_cast<const u32t*>(bl_base + kt * 32);
            u32t bl1 = *reinterpret_cast<const u32t*>(bl_base + kt * 32 + 16);
#pragma unroll
            for (int g = 0; g < 4; g++) {
                u32t a[4] = {wh[g][kt].x, wh[g][kt].y, wh[g][kt].z, wh[g][kt].w};
                u32t al[4];
                if (g == 0) {
                    al[0] = wlr[kt].x; al[1] = wlr[kt].y;
                    al[2] = wlr[kt].z; al[3] = wlr[kt].w;
                } else {
                    uint4 alv = wlS[(((g * 8 + w) * 8) + kt) * 32 + l];
                    al[0] = alv.x; al[1] = alv.y; al[2] = alv.z; al[3] = alv.w;
                }
                mma_bf16(d1[g], a,  bh0, bh1);   // Wh @ hh
                mma_bf16(d2[g], a,  bl0, bl1);   // Wh @ hl
                mma_bf16(d2[g], al, bh0, bh1);   // Wl @ hh
            }
        }

        // in-register activation (lanes holding real chains only)
        if (active) {
            char* wbh = smc + ((t & 1) ? LS_HH0 : LS_HH1);
            char* wbl = wbh + (LS_HL0 - LS_HH0);
#pragma unroll
            for (int q = 0; q < 4; q++) {
                int rh = q >> 1, cc = q & 1;
                float xnc = cc ? xnv.y : xnv.x;
                float gi = d1[0][q] + d2[0][q] + shv[0][rh] + w0g[0][rh] * xnc;
                float gf = d1[1][q] + d2[1][q] + shv[1][rh] + w0g[1][rh] * xnc;
                float gg = d1[2][q] + d2[2][q] + shv[2][rh] + w0g[2][rh] * xnc;
                float go = d1[3][q] + d2[3][q] + shv[3][rh] + w0g[3][rh] * xnc;
                float ig = sig_f(gi), fg = sig_f(gf), g = tanh_f(gg), og = sig_f(go);
                float cn = fmaf(fg, cst[q], ig * g);
                cst[q] = cn;
                float hv = og * tanh_f(cn);
                __nv_bfloat16 bh = __float2bfloat16(hv);
                float rem = hv - __bfloat162float(bh);
                __nv_bfloat16 bl = __float2bfloat16(rem);
                int r  = r0 + rh * 8;
                int ch = c0 + cc;
                *reinterpret_cast<__nv_bfloat16*>(wbh + ch * HSTR + r * 2) = bh;
                *reinterpret_cast<__nv_bfloat16*>(wbl + ch * HSTR + r * 2) = bl;
                size_t gb = ((size_t)t * OBS + j0 + ch) * PE + r;
                g_HBh[gb] = bh;
                g_HBl[gb] = bl;
            }
        }
        __syncthreads();   // h writes (buf t+1) visible; reads of buf t done
    }
}

// ======================================================================
// K4: attention via warp-level mma.sync bf16 (unchanged from R13-pass).
// grid(8 i-tiles, 256 t), block(256) = 8 warps; warp w owns i-rows 16w..16w+15.
// ======================================================================
#define PADB 272
#define SM_AH  0u
#define SM_AL  34816u
#define SM_B0H 69632u
#define SM_B0L 104448u
#define SM_B1H 139264u
#define SM_B1L 174080u
#define SM_XN  208896u
#define SM_RED 210944u
#define SM_ATTN_TOTAL 211456

__global__ void __launch_bounds__(256, 1) k_attn(float* __restrict__ out) {
    extern __shared__ char smc[];
    u32t smb = (u32t)__cvta_generic_to_shared(smc);
    float* xnS  = reinterpret_cast<float*>(smc + SM_XN);
    float* redS = reinterpret_cast<float*>(smc + SM_RED);

    int tid  = threadIdx.x;
    int w    = tid >> 5;
    int lane = tid & 31;
    int t  = blockIdx.y;
    int i0 = blockIdx.x * 128;

    const __nv_bfloat16* Hh = g_HBh + (size_t)t * OBS * PE;
    const __nv_bfloat16* Hl = g_HBl + (size_t)t * OBS * PE;

    for (int idx = tid; idx < 2048; idx += 256) {
        int row = idx >> 4, c = idx & 15;
        u32t doff = (u32t)(row * PADB + c * 16);
        cp16(smb + SM_AH + doff, g_QAh + (size_t)(i0 + row) * PE + c * 8);
        cp16(smb + SM_AL + doff, g_QAl + (size_t)(i0 + row) * PE + c * 8);
        cp16(smb + SM_B0H + doff, Hh + (size_t)row * PE + c * 8);
        cp16(smb + SM_B0L + doff, Hl + (size_t)row * PE + c * 8);
    }
    cp_commit();
    for (int idx = tid; idx < OBS; idx += 256) xnS[idx] = g_XN[t * OBS + idx];

    int grp = lane >> 3, lr = lane & 7;
    u32t a_off = (u32t)((16 * w + (grp & 1) * 8 + lr) * PADB + (grp >> 1) * 16);
    u32t b_off = (u32t)(((grp >> 1) * 8 + lr) * PADB + (grp & 1) * 16);

    float qb0 = g_qbs[i0 + 16 * w + (lane >> 2)];
    float qb1 = g_qbs[i0 + 16 * w + (lane >> 2) + 8];
    float outa0 = 0.f, outa1 = 0.f;

    for (int jt = 0; jt < 4; jt++) {
        cp_wait0();
        __syncthreads();
        if (jt < 3) {
            u32t dbh = ((jt + 1) & 1) ? SM_B1H : SM_B0H;
            u32t dbl = ((jt + 1) & 1) ? SM_B1L : SM_B0L;
            for (int idx = tid; idx < 2048; idx += 256) {
                int row = idx >> 4, c = idx & 15;
                u32t doff = (u32t)(row * PADB + c * 16);
                size_t src = (size_t)((jt + 1) * 128 + row) * PE + c * 8;
                cp16(smb + dbh + doff, Hh + src);
                cp16(smb + dbl + doff, Hl + src);
            }
            cp_commit();
        }

        u32t bhb = smb + ((jt & 1) ? SM_B1H : SM_B0H) + b_off;
        u32t blb = smb + ((jt & 1) ? SM_B1L : SM_B0L) + b_off;
        u32t ahb = smb + SM_AH + a_off;
        u32t alb = smb + SM_AL + a_off;

        float d[16][4];
#pragma unroll
        for (int nt = 0; nt < 16; nt++)
#pragma unroll
            for (int q = 0; q < 4; q++) d[nt][q] = 0.f;

        for (int ks = 0; ks < 8; ks++) {
            u32t ah[4], al[4];
            LDSM4(ah, ahb + ks * 32);
            LDSM4(al, alb + ks * 32);
#pragma unroll
            for (int ntp = 0; ntp < 8; ntp++) {
                u32t bh[4], bl[4];
                LDSM4(bh, bhb + ntp * (16 * PADB) + ks * 32);
                LDSM4(bl, blb + ntp * (16 * PADB) + ks * 32);
                mma_bf16(d[2 * ntp],     ah, bh[0], bh[1]);
                mma_bf16(d[2 * ntp],     ah, bl[0], bl[1]);
                mma_bf16(d[2 * ntp],     al, bh[0], bh[1]);
                mma_bf16(d[2 * ntp + 1], ah, bh[2], bh[3]);
                mma_bf16(d[2 * ntp + 1], ah, bl[2], bl[3]);
                mma_bf16(d[2 * ntp + 1], al, bh[2], bh[3]);
            }
        }

#pragma unroll
        for (int nt = 0; nt < 16; nt++) {
            float2 xr = *reinterpret_cast<const float2*>(
                xnS + jt * 128 + nt * 8 + (lane & 3) * 2);
            outa0 = fmaf(tanh_f(d[nt][0] + qb0), xr.x, outa0);
            outa0 = fmaf(tanh_f(d[nt][1] + qb0), xr.y, outa0);
            outa1 = fmaf(tanh_f(d[nt][2] + qb1), xr.x, outa1);
            outa1 = fmaf(tanh_f(d[nt][3] + qb1), xr.y, outa1);
        }
    }

#pragma unroll
    for (int mm = 1; mm <= 2; mm <<= 1) {
        outa0 += __shfl_xor_sync(0xFFFFFFFFu, outa0, mm);
        outa1 += __shfl_xor_sync(0xFFFFFFFFu, outa1, mm);
    }
    __syncthreads();
    if ((lane & 3) == 0) {
        redS[16 * w + (lane >> 2)]     = outa0;
        redS[16 * w + (lane >> 2) + 8] = outa1;
    }
    __syncthreads();
    if (tid < 128)
        out[t * HID + i0 + tid] = tanh_f(redS[tid]);
}

// ======================================================================
// launcher
// ======================================================================
extern "C" void kernel_launch(void* const* d_in, const int* in_sizes, int n_in,
                              void* d_out, int out_size) {
    const float* obs    = (const float*)d_in[0];   // (256,512)
    const float* pact   = (const float*)d_in[1];   // (256,32)
    const float* shift  = (const float*)d_in[2];   // (512,)
    const float* scale  = (const float*)d_in[3];   // (512,)
    const float* pos    = (const float*)d_in[4];   // (1024,128)
    const float* W_ih   = (const float*)d_in[5];   // (512,33)
    const float* b_ih   = (const float*)d_in[6];   // (512,)
    const float* W_hh   = (const float*)d_in[7];   // (512,128)
    const float* b_hh   = (const float*)d_in[8];   // (512,)
    const float* Wq     = (const float*)d_in[9];   // (128,128)
    const float* bq     = (const float*)d_in[10];  // (128,)
    const float* Wk     = (const float*)d_in[11];  // (128,128)
    const float* bk     = (const float*)d_in[12];  // (128,)
    float* out = (float*)d_out;                    // (256,1024)

    cudaFuncSetAttribute(k_q,       cudaFuncAttributeMaxDynamicSharedMemorySize, 69632);
    cudaFuncSetAttribute(k_qw,      cudaFuncAttributeMaxDynamicSharedMemorySize, 69632);
    cudaFuncSetAttribute(k_lstm_tc, cudaFuncAttributeMaxDynamicSharedMemorySize, LS_TOT);
    cudaFuncSetAttribute(k_attn,    cudaFuncAttributeMaxDynamicSharedMemorySize, SM_ATTN_TOTAL);

    k_pre1<<<T_STEPS, 512>>>(obs, pact, shift, scale, W_ih, b_ih, b_hh);
    k_prew<<<256, 128>>>(W_hh);
    k_q   <<<128, 256, 69632>>>(pos, Wq, bq);
    k_lstm_tc<<<128, 256, LS_TOT>>>();
    k_qw  <<<128, 256, 69632>>>(Wk, bk);
    k_split<<<128, 256>>>();
    k_attn<<<dim3(8, T_STEPS), 256, SM_ATTN_TOTAL>>>(out);
}